// round 3
// baseline (speedup 1.0000x reference)
#include <cuda_runtime.h>
#include <cuda_bf16.h>
#include <cstdint>
#include <mma.h>

using namespace nvcuda;

#define B_  128
#define T_  512
#define C_  384
#define NH_ 6
#define HD_ 64

// ---------------- scratch (device globals: allocation-free) ----------------
__device__ float g_q[(size_t)B_ * NH_ * T_ * HD_];  // [B,NH,T,HD]
__device__ float g_k[(size_t)B_ * NH_ * T_ * HD_];
__device__ float g_v[(size_t)B_ * NH_ * T_ * HD_];
__device__ float g_o[(size_t)B_ * T_ * C_];         // [B,T,C]

// ---------------- cp.async helpers ----------------
__device__ __forceinline__ void cp_async16(void* smem, const void* gmem) {
    unsigned s = (unsigned)__cvta_generic_to_shared(smem);
    asm volatile("cp.async.cg.shared.global [%0], [%1], 16;\n" :: "r"(s), "l"(gmem));
}
__device__ __forceinline__ void cp_commit() {
    asm volatile("cp.async.commit_group;\n");
}
__device__ __forceinline__ void cp_wait_all() {
    asm volatile("cp.async.wait_group 0;\n");
}

#define BM 128
#define BN 64
#define BK 32
#define LDA 36
// dynamic smem for GEMM: double-buffered A (2*128*36) + B (2*64*36) floats
#define GEMM_SMEM ((2 * BM * LDA + 2 * BN * LDA) * 4)

// ---------------------------------------------------------------------------
// Pipelined GEMM mainloop (NT): acc = A[M,K] @ B[N,K]^T on a 128x64 tile.
// 256 threads / 8 warps, warp tile 32x32 (2x2 wmma 16x16x8 tf32).
// EPI = 0: plain store to Cc.  EPI = 1: RoPE + split + transpose epilogue.
// ---------------------------------------------------------------------------
template <int EPI>
__global__ void __launch_bounds__(256) gemm_nt_pipe(
    const float* __restrict__ A, const float* __restrict__ Bw,
    float* __restrict__ Cc,
    const float* __restrict__ cosb, const float* __restrict__ sinb,
    float* __restrict__ qo, float* __restrict__ ko, float* __restrict__ vo,
    int M, int N, int K)
{
    extern __shared__ float sh[];
    float* sA = sh;                     // [2][BM][LDA]
    float* sB = sh + 2 * BM * LDA;      // [2][BN][LDA]

    const int tid = threadIdx.x;
    const int w   = tid >> 5;
    const int bm  = blockIdx.y * BM;
    const int bn  = blockIdx.x * BN;
    const int m_off = (w >> 1) * 32;
    const int n_off = (w & 1) * 32;

    const int lr = tid >> 3;            // 0..31
    const int lc = (tid & 7) * 4;       // 0,4,..28

    wmma::fragment<wmma::accumulator, 16, 16, 8, float> acc[2][2];
    #pragma unroll
    for (int i = 0; i < 2; i++)
        #pragma unroll
        for (int j = 0; j < 2; j++)
            wmma::fill_fragment(acc[i][j], 0.0f);

    auto load_stage = [&](int k0, int st) {
        float* dA = sA + st * BM * LDA;
        float* dB = sB + st * BN * LDA;
        #pragma unroll
        for (int p = 0; p < 4; p++) {
            int r = lr + p * 32;
            cp_async16(&dA[r * LDA + lc], &A[(size_t)(bm + r) * K + k0 + lc]);
        }
        #pragma unroll
        for (int p = 0; p < 2; p++) {
            int r = lr + p * 32;
            cp_async16(&dB[r * LDA + lc], &Bw[(size_t)(bn + r) * K + k0 + lc]);
        }
        cp_commit();
    };

    load_stage(0, 0);
    const int nk = K / BK;

    for (int ki = 0; ki < nk; ki++) {
        cp_wait_all();
        __syncthreads();
        if (ki + 1 < nk) load_stage((ki + 1) * BK, (ki + 1) & 1);

        const float* cA = sA + (ki & 1) * BM * LDA;
        const float* cB = sB + (ki & 1) * BN * LDA;

        #pragma unroll
        for (int kk = 0; kk < BK; kk += 8) {
            wmma::fragment<wmma::matrix_a, 16, 16, 8, wmma::precision::tf32, wmma::row_major> af[2];
            wmma::fragment<wmma::matrix_b, 16, 16, 8, wmma::precision::tf32, wmma::col_major> bf[2];
            #pragma unroll
            for (int i = 0; i < 2; i++) {
                wmma::load_matrix_sync(af[i], &cA[(m_off + 16 * i) * LDA + kk], LDA);
                #pragma unroll
                for (int e = 0; e < af[i].num_elements; e++)
                    af[i].x[e] = wmma::__float_to_tf32(af[i].x[e]);
            }
            #pragma unroll
            for (int j = 0; j < 2; j++) {
                wmma::load_matrix_sync(bf[j], &cB[(n_off + 16 * j) * LDA + kk], LDA);
                #pragma unroll
                for (int e = 0; e < bf[j].num_elements; e++)
                    bf[j].x[e] = wmma::__float_to_tf32(bf[j].x[e]);
            }
            #pragma unroll
            for (int i = 0; i < 2; i++)
                #pragma unroll
                for (int j = 0; j < 2; j++)
                    wmma::mma_sync(acc[i][j], af[i], bf[j], acc[i][j]);
        }
        __syncthreads();
    }

    if (EPI == 0) {
        #pragma unroll
        for (int i = 0; i < 2; i++)
            #pragma unroll
            for (int j = 0; j < 2; j++)
                wmma::store_matrix_sync(
                    &Cc[(size_t)(bm + m_off + 16 * i) * N + bn + n_off + 16 * j],
                    acc[i][j], N, wmma::mem_row_major);
    } else {
        // RoPE + split + transpose epilogue. Reuse sA region as a 128x68 C tile.
        float* sC = sh;   // 128*68 = 8704 floats <= 2*128*36 = 9216 floats
        #pragma unroll
        for (int i = 0; i < 2; i++)
            #pragma unroll
            for (int j = 0; j < 2; j++)
                wmma::store_matrix_sync(&sC[(m_off + 16 * i) * 68 + n_off + 16 * j],
                                        acc[i][j], 68, wmma::mem_row_major);
        __syncthreads();

        const int g  = bn >> 6;     // 0..17
        const int i3 = g / NH_;     // 0:q 1:k 2:v
        const int hh = g % NH_;

        #pragma unroll
        for (int it = 0; it < 32; it++) {
            int idx = it * 256 + tid;
            int r = idx >> 6, d = idx & 63;
            int gm = bm + r;
            int b = gm >> 9, t = gm & 511;
            float val = sC[r * 68 + d];
            if (i3 < 2 && d < 16) {
                if (d < 8) {
                    float c = cosb[t * 8 + d], s = sinb[t * 8 + d];
                    val = val * c - sC[r * 68 + d + 8] * s;
                } else {
                    int jj = d - 8;
                    float c = cosb[t * 8 + jj], s = sinb[t * 8 + jj];
                    val = val * c + sC[r * 68 + d - 8] * s;
                }
            }
            size_t off = (((size_t)b * NH_ + hh) * T_ + t) * HD_ + d;
            if (i3 == 0)      qo[off] = val * 0.125f;   // fold in 1/sqrt(64)
            else if (i3 == 1) ko[off] = val;
            else              vo[off] = val;
        }
    }
}

// ---------------------------------------------------------------------------
// Attention: one block per (b, h, q-tile of 64). Full score strip [64 x 512]
// in smem. Q pre-scaled. cp.async double-buffered K/V tiles; V0 prefetched
// during softmax. S = Q K^T, softmax fp32, O = P V -> g_o [B,T,C].
// ---------------------------------------------------------------------------
#define SLD 520
#define QLD 72
#define ATTN_SMEM ((3 * 64 * QLD + 64 * SLD) * 4)

__global__ void __launch_bounds__(256) attn_kernel(
    const float* __restrict__ q, const float* __restrict__ k,
    const float* __restrict__ v, float* __restrict__ o)
{
    extern __shared__ float sh[];
    float* sQ  = sh;                  // 64 x 72
    float* sKV = sh + 64 * QLD;       // 2 x (64 x 72)
    float* sS  = sh + 3 * 64 * QLD;   // 64 x 520

    const int qt = blockIdx.x, h = blockIdx.y, b = blockIdx.z;
    const int tid = threadIdx.x, w = tid >> 5, lane = tid & 31;
    const int nkt = qt + 1;

    const float* qbase = q + (((size_t)b * NH_ + h) * T_ + qt * 64) * HD_;
    const float* kbase = k + (((size_t)b * NH_ + h) * T_) * HD_;
    const float* vbase = v + (((size_t)b * NH_ + h) * T_) * HD_;

    const int lr = tid >> 2;          // 0..63
    const int lc = (tid & 3) * 16;    // 0,16,32,48

    auto load_tile = [&](const float* base, int kt, float* dst) {
        #pragma unroll
        for (int p = 0; p < 4; p++) {
            int c4 = lc + p * 4;
            cp_async16(&dst[lr * QLD + c4], &base[(kt * 64 + lr) * 64 + c4]);
        }
        cp_commit();
    };

    // Q tile + K0 tile prefetch
    {
        #pragma unroll
        for (int p = 0; p < 4; p++) {
            int c4 = lc + p * 4;
            cp_async16(&sQ[lr * QLD + c4], &qbase[lr * 64 + c4]);
        }
        load_tile(kbase, 0, sKV);
    }

    const int m_off = (w >> 1) * 16;   // 4 warp rows x 16
    const int n_off = (w & 1) * 32;    // 2 warp cols x 32

    // ---- S phase ----
    for (int kt = 0; kt < nkt; kt++) {
        cp_wait_all();
        __syncthreads();
        if (kt + 1 < nkt) load_tile(kbase, kt + 1, sKV + ((kt + 1) & 1) * 64 * QLD);
        const float* cK = sKV + (kt & 1) * 64 * QLD;

        wmma::fragment<wmma::accumulator, 16, 16, 8, float> sc[2];
        #pragma unroll
        for (int j = 0; j < 2; j++) wmma::fill_fragment(sc[j], 0.0f);

        #pragma unroll
        for (int kk = 0; kk < 64; kk += 8) {
            wmma::fragment<wmma::matrix_a, 16, 16, 8, wmma::precision::tf32, wmma::row_major> af;
            wmma::load_matrix_sync(af, &sQ[m_off * QLD + kk], QLD);
            #pragma unroll
            for (int e = 0; e < af.num_elements; e++)
                af.x[e] = wmma::__float_to_tf32(af.x[e]);
            #pragma unroll
            for (int j = 0; j < 2; j++) {
                wmma::fragment<wmma::matrix_b, 16, 16, 8, wmma::precision::tf32, wmma::col_major> bf;
                wmma::load_matrix_sync(bf, &cK[(n_off + 16 * j) * QLD + kk], QLD);
                #pragma unroll
                for (int e = 0; e < bf.num_elements; e++)
                    bf.x[e] = wmma::__float_to_tf32(bf.x[e]);
                wmma::mma_sync(sc[j], af, bf, sc[j]);
            }
        }
        #pragma unroll
        for (int j = 0; j < 2; j++)
            wmma::store_matrix_sync(&sS[m_off * SLD + kt * 64 + n_off + 16 * j],
                                    sc[j], SLD, wmma::mem_row_major);
        __syncthreads();
    }

    // Prefetch V0 while softmax runs
    load_tile(vbase, 0, sKV);

    // ---- softmax (causal): warp w handles rows w*8 .. w*8+7 ----
    const int L = nkt * 64;
    for (int rr = 0; rr < 8; rr++) {
        int r    = w * 8 + rr;
        int vlen = qt * 64 + r + 1;
        float mx = -1e30f;
        for (int j = lane; j < vlen; j += 32) mx = fmaxf(mx, sS[r * SLD + j]);
        #pragma unroll
        for (int off = 16; off > 0; off >>= 1)
            mx = fmaxf(mx, __shfl_xor_sync(0xffffffffu, mx, off));
        float sum = 0.f;
        for (int j = lane; j < vlen; j += 32) {
            float e = __expf(sS[r * SLD + j] - mx);
            sS[r * SLD + j] = e;
            sum += e;
        }
        #pragma unroll
        for (int off = 16; off > 0; off >>= 1)
            sum += __shfl_xor_sync(0xffffffffu, sum, off);
        float inv = 1.0f / sum;
        for (int j = lane; j < vlen; j += 32) sS[r * SLD + j] *= inv;
        for (int j = vlen + lane; j < L; j += 32) sS[r * SLD + j] = 0.f;
    }

    // ---- O phase ----
    wmma::fragment<wmma::accumulator, 16, 16, 8, float> oacc[2];
    #pragma unroll
    for (int j = 0; j < 2; j++) wmma::fill_fragment(oacc[j], 0.0f);

    for (int kt = 0; kt < nkt; kt++) {
        cp_wait_all();
        __syncthreads();
        if (kt + 1 < nkt) load_tile(vbase, kt + 1, sKV + ((kt + 1) & 1) * 64 * QLD);
        const float* cV = sKV + (kt & 1) * 64 * QLD;

        #pragma unroll
        for (int kk = 0; kk < 64; kk += 8) {
            wmma::fragment<wmma::matrix_a, 16, 16, 8, wmma::precision::tf32, wmma::row_major> af;
            wmma::load_matrix_sync(af, &sS[m_off * SLD + kt * 64 + kk], SLD);
            #pragma unroll
            for (int e = 0; e < af.num_elements; e++)
                af.x[e] = wmma::__float_to_tf32(af.x[e]);
            #pragma unroll
            for (int j = 0; j < 2; j++) {
                wmma::fragment<wmma::matrix_b, 16, 16, 8, wmma::precision::tf32, wmma::row_major> bf;
                wmma::load_matrix_sync(bf, &cV[kk * QLD + n_off + 16 * j], QLD);
                #pragma unroll
                for (int e = 0; e < bf.num_elements; e++)
                    bf.x[e] = wmma::__float_to_tf32(bf.x[e]);
                wmma::mma_sync(oacc[j], af, bf, oacc[j]);
            }
        }
        __syncthreads();
    }

    #pragma unroll
    for (int j = 0; j < 2; j++)
        wmma::store_matrix_sync(
            &o[((size_t)b * T_ + qt * 64 + m_off) * C_ + h * HD_ + n_off + 16 * j],
            oacc[j], C_, wmma::mem_row_major);
}

// ---------------------------------------------------------------------------
extern "C" void kernel_launch(void* const* d_in, const int* in_sizes, int n_in,
                              void* d_out, int out_size)
{
    const float* x    = (const float*)d_in[0]; // [B,T,C]
    const float* Wqkv = (const float*)d_in[1]; // [3C,C]
    const float* Wout = (const float*)d_in[2]; // [C,C]
    const float* cosb = (const float*)d_in[3]; // [1,1,512,8]
    const float* sinb = (const float*)d_in[4];
    float* out = (float*)d_out;                // [B,T,C]

    float *q, *k, *v, *o;
    cudaGetSymbolAddress((void**)&q, g_q);
    cudaGetSymbolAddress((void**)&k, g_k);
    cudaGetSymbolAddress((void**)&v, g_v);
    cudaGetSymbolAddress((void**)&o, g_o);

    const int M = B_ * T_; // 65536

    static bool attr_done = false;
    if (!attr_done) {
        cudaFuncSetAttribute(gemm_nt_pipe<0>,
                             cudaFuncAttributeMaxDynamicSharedMemorySize, GEMM_SMEM);
        cudaFuncSetAttribute(gemm_nt_pipe<1>,
                             cudaFuncAttributeMaxDynamicSharedMemorySize, GEMM_SMEM);
        cudaFuncSetAttribute(attn_kernel,
                             cudaFuncAttributeMaxDynamicSharedMemorySize, ATTN_SMEM);
        attr_done = true;
    }

    // K1: qkv GEMM + fused RoPE/split/transpose (q pre-scaled by 1/8)
    {
        dim3 grid((3 * C_) / BN, M / BM);
        gemm_nt_pipe<1><<<grid, 256, GEMM_SMEM>>>(
            x, Wqkv, nullptr, cosb, sinb, q, k, v, M, 3 * C_, C_);
    }
    // K2: causal attention
    {
        dim3 grid(T_ / 64, NH_, B_);
        attn_kernel<<<grid, 256, ATTN_SMEM>>>(q, k, v, o);
    }
    // K3: out = o @ Wout^T
    {
        dim3 grid(C_ / BN, M / BM);
        gemm_nt_pipe<0><<<grid, 256, GEMM_SMEM>>>(
            o, Wout, out, nullptr, nullptr, nullptr, nullptr, nullptr, M, C_, C_);
    }
}

// round 5
// speedup vs baseline: 2.1899x; 2.1899x over previous
#include <cuda_runtime.h>
#include <cuda_fp16.h>
#include <cstdint>
#include <mma.h>

using namespace nvcuda;

#define B_  128
#define T_  512
#define C_  384
#define NH_ 6
#define HD_ 64

// ---------------- scratch (device globals: allocation-free) ----------------
__device__ __half g_xh[(size_t)B_ * T_ * C_];
__device__ __half g_wqkvh[(size_t)3 * C_ * C_];
__device__ __half g_wouth[(size_t)C_ * C_];
__device__ __half g_qh[(size_t)B_ * NH_ * T_ * HD_];
__device__ __half g_kh[(size_t)B_ * NH_ * T_ * HD_];
__device__ __half g_vh[(size_t)B_ * NH_ * T_ * HD_];
__device__ __half g_oh[(size_t)B_ * T_ * C_];

// ---------------- cp.async helpers ----------------
__device__ __forceinline__ void cp_async16(void* smem, const void* gmem) {
    unsigned s = (unsigned)__cvta_generic_to_shared(smem);
    asm volatile("cp.async.cg.shared.global [%0], [%1], 16;\n" :: "r"(s), "l"(gmem));
}
__device__ __forceinline__ void cp_commit() {
    asm volatile("cp.async.commit_group;\n");
}
__device__ __forceinline__ void cp_wait_all() {
    asm volatile("cp.async.wait_group 0;\n");
}

// ---------------------------------------------------------------------------
// fp32 -> fp16 converter (vectorized, n multiple of 2048)
// ---------------------------------------------------------------------------
__global__ void cvt_f2h(const float* __restrict__ in, __half* __restrict__ out) {
    size_t i = ((size_t)blockIdx.x * blockDim.x + threadIdx.x) * 8;
    float4 a = *(const float4*)(in + i);
    float4 b = *(const float4*)(in + i + 4);
    __half2 h0 = __floats2half2_rn(a.x, a.y);
    __half2 h1 = __floats2half2_rn(a.z, a.w);
    __half2 h2 = __floats2half2_rn(b.x, b.y);
    __half2 h3 = __floats2half2_rn(b.z, b.w);
    uint4 pack;
    pack.x = *(unsigned*)&h0; pack.y = *(unsigned*)&h1;
    pack.z = *(unsigned*)&h2; pack.w = *(unsigned*)&h3;
    *(uint4*)(out + i) = pack;
}

// ===========================================================================
// fp16 GEMM (NT): C[M,N] = A[M,K] @ B[N,K]^T, fp32 accumulate.
// BM=128, BN=64, BK=32, 256 threads / 8 warps, warp tile 32x32
// (2x2 wmma 16x16x16). cp.async double buffered.
// EPI=0: fp32 store to Cc.  EPI=1: RoPE + split + transpose -> fp16 q/k/v.
// ===========================================================================
#define LDH 40
#define GEMM_SMEM_H 34816   // max(load bufs 30720, epilogue stage 128*68*4)

template <int EPI>
__global__ void __launch_bounds__(256) gemm_h(
    const __half* __restrict__ A, const __half* __restrict__ Bw,
    float* __restrict__ Cc,
    const float* __restrict__ cosb, const float* __restrict__ sinb,
    __half* __restrict__ qo, __half* __restrict__ ko, __half* __restrict__ vo,
    int M, int N, int K)
{
    extern __shared__ char smem[];
    __half* sAh = (__half*)smem;                       // [2][128][LDH]
    __half* sBh = (__half*)smem + 2 * 128 * LDH;       // [2][64][LDH]

    const int tid = threadIdx.x;
    const int w   = tid >> 5;
    const int bm  = blockIdx.y * 128;
    const int bn  = blockIdx.x * 64;
    const int m_off = (w >> 1) * 32;
    const int n_off = (w & 1) * 32;

    wmma::fragment<wmma::accumulator, 16, 16, 16, float> acc[2][2];
    #pragma unroll
    for (int i = 0; i < 2; i++)
        #pragma unroll
        for (int j = 0; j < 2; j++)
            wmma::fill_fragment(acc[i][j], 0.0f);

    auto load_stage = [&](int k0, int st) {
        __half* dA = sAh + st * 128 * LDH;
        __half* dB = sBh + st * 64 * LDH;
        // A: 128 rows x 32 halves = 512 chunks of 8 halves
        #pragma unroll
        for (int p = 0; p < 2; p++) {
            int c = p * 256 + tid;
            int r = c >> 2, c8 = (c & 3) * 8;
            cp_async16(&dA[r * LDH + c8], &A[(size_t)(bm + r) * K + k0 + c8]);
        }
        // B: 64 rows x 32 halves = 256 chunks
        {
            int r = tid >> 2, c8 = (tid & 3) * 8;
            cp_async16(&dB[r * LDH + c8], &Bw[(size_t)(bn + r) * K + k0 + c8]);
        }
        cp_commit();
    };

    load_stage(0, 0);
    const int nk = K / 32;

    for (int ki = 0; ki < nk; ki++) {
        cp_wait_all();
        __syncthreads();
        if (ki + 1 < nk) load_stage((ki + 1) * 32, (ki + 1) & 1);

        const __half* cA = sAh + (ki & 1) * 128 * LDH;
        const __half* cB = sBh + (ki & 1) * 64 * LDH;

        #pragma unroll
        for (int kk = 0; kk < 32; kk += 16) {
            wmma::fragment<wmma::matrix_a, 16, 16, 16, __half, wmma::row_major> af[2];
            wmma::fragment<wmma::matrix_b, 16, 16, 16, __half, wmma::col_major> bf[2];
            #pragma unroll
            for (int i = 0; i < 2; i++)
                wmma::load_matrix_sync(af[i], &cA[(m_off + 16 * i) * LDH + kk], LDH);
            #pragma unroll
            for (int j = 0; j < 2; j++)
                wmma::load_matrix_sync(bf[j], &cB[(n_off + 16 * j) * LDH + kk], LDH);
            #pragma unroll
            for (int i = 0; i < 2; i++)
                #pragma unroll
                for (int j = 0; j < 2; j++)
                    wmma::mma_sync(acc[i][j], af[i], bf[j], acc[i][j]);
        }
        __syncthreads();
    }

    if (EPI == 0) {
        #pragma unroll
        for (int i = 0; i < 2; i++)
            #pragma unroll
            for (int j = 0; j < 2; j++)
                wmma::store_matrix_sync(
                    &Cc[(size_t)(bm + m_off + 16 * i) * N + bn + n_off + 16 * j],
                    acc[i][j], N, wmma::mem_row_major);
    } else {
        // Stage 128x64 fp32 tile, apply RoPE, emit fp16 q/k/v.
        float* sC = (float*)smem;   // 128 x 68
        #pragma unroll
        for (int i = 0; i < 2; i++)
            #pragma unroll
            for (int j = 0; j < 2; j++)
                wmma::store_matrix_sync(&sC[(m_off + 16 * i) * 68 + n_off + 16 * j],
                                        acc[i][j], 68, wmma::mem_row_major);
        __syncthreads();

        const int g  = bn >> 6;     // 0..17
        const int i3 = g / NH_;     // 0:q 1:k 2:v
        const int hh = g % NH_;

        #pragma unroll
        for (int it = 0; it < 32; it++) {
            int idx = it * 256 + tid;
            int r = idx >> 6, d = idx & 63;
            int gm = bm + r;
            int b = gm >> 9, t = gm & 511;
            float val = sC[r * 68 + d];
            if (i3 < 2 && d < 16) {
                if (d < 8) {
                    float c = cosb[t * 8 + d], s = sinb[t * 8 + d];
                    val = val * c - sC[r * 68 + d + 8] * s;
                } else {
                    int jj = d - 8;
                    float c = cosb[t * 8 + jj], s = sinb[t * 8 + jj];
                    val = val * c + sC[r * 68 + d - 8] * s;
                }
            }
            size_t off = (((size_t)b * NH_ + hh) * T_ + t) * HD_ + d;
            if (i3 == 0)      qo[off] = __float2half_rn(val * 0.125f);
            else if (i3 == 1) ko[off] = __float2half_rn(val);
            else              vo[off] = __float2half_rn(val);
        }
    }
}

// ===========================================================================
// Attention (fp16 mma, fp32 softmax): one block per (b, h, q-tile of 64).
// smem: sQ h[64][72] | sKV h[2][64][72] | sP h[64][72] | sS f[64][520]
// ===========================================================================
#define QLDH 72
#define SLD  520
#define OFF_KV  9216
#define OFF_P   27648
#define OFF_S   36864
#define ATTN_SMEM (OFF_S + 64 * SLD * 4)   // 169984 B

__global__ void __launch_bounds__(256) attn_kernel(
    const __half* __restrict__ q, const __half* __restrict__ k,
    const __half* __restrict__ v, __half* __restrict__ o)
{
    extern __shared__ char smem[];
    __half* sQ  = (__half*)smem;
    __half* sKV = (__half*)(smem + OFF_KV);
    __half* sP  = (__half*)(smem + OFF_P);
    float*  sS  = (float*)(smem + OFF_S);

    const int qt = blockIdx.x, h = blockIdx.y, b = blockIdx.z;
    const int tid = threadIdx.x, w = tid >> 5, lane = tid & 31;
    const int nkt = qt + 1;

    const __half* qbase = q + (((size_t)b * NH_ + h) * T_ + qt * 64) * HD_;
    const __half* kbase = k + (((size_t)b * NH_ + h) * T_) * HD_;
    const __half* vbase = v + (((size_t)b * NH_ + h) * T_) * HD_;

    const int lr  = tid >> 2;          // 0..63
    const int lc8 = (tid & 3) * 8;     // 0,8,16,24

    auto load_tile = [&](const __half* base, int kt, __half* dst) {
        #pragma unroll
        for (int p = 0; p < 2; p++) {
            int c = lc8 + p * 32;
            cp_async16(&dst[lr * QLDH + c], &base[(kt * 64 + lr) * 64 + c]);
        }
        cp_commit();
    };

    // Q tile + K0 prefetch (same commit group)
    {
        #pragma unroll
        for (int p = 0; p < 2; p++) {
            int c = lc8 + p * 32;
            cp_async16(&sQ[lr * QLDH + c], &qbase[lr * 64 + c]);
        }
        load_tile(kbase, 0, sKV);
    }

    const int m_off = (w >> 1) * 16;
    const int n_off = (w & 1) * 32;

    // ---- S phase ----
    for (int kt = 0; kt < nkt; kt++) {
        cp_wait_all();
        __syncthreads();
        if (kt + 1 < nkt) load_tile(kbase, kt + 1, sKV + ((kt + 1) & 1) * 64 * QLDH);
        const __half* cK = sKV + (kt & 1) * 64 * QLDH;

        wmma::fragment<wmma::accumulator, 16, 16, 16, float> sc[2];
        #pragma unroll
        for (int j = 0; j < 2; j++) wmma::fill_fragment(sc[j], 0.0f);

        #pragma unroll
        for (int kk = 0; kk < 64; kk += 16) {
            wmma::fragment<wmma::matrix_a, 16, 16, 16, __half, wmma::row_major> af;
            wmma::load_matrix_sync(af, &sQ[m_off * QLDH + kk], QLDH);
            #pragma unroll
            for (int j = 0; j < 2; j++) {
                wmma::fragment<wmma::matrix_b, 16, 16, 16, __half, wmma::col_major> bf;
                wmma::load_matrix_sync(bf, &cK[(n_off + 16 * j) * QLDH + kk], QLDH);
                wmma::mma_sync(sc[j], af, bf, sc[j]);
            }
        }
        #pragma unroll
        for (int j = 0; j < 2; j++)
            wmma::store_matrix_sync(&sS[m_off * SLD + kt * 64 + n_off + 16 * j],
                                    sc[j], SLD, wmma::mem_row_major);
        __syncthreads();
    }

    // Prefetch V0 while softmax runs
    load_tile(vbase, 0, sKV);

    // ---- softmax (causal, fp32): warp w handles rows w*8 .. w*8+7 ----
    const int L = nkt * 64;
    for (int rr = 0; rr < 8; rr++) {
        int r    = w * 8 + rr;
        int vlen = qt * 64 + r + 1;
        float mx = -1e30f;
        for (int j = lane; j < vlen; j += 32) mx = fmaxf(mx, sS[r * SLD + j]);
        #pragma unroll
        for (int off = 16; off > 0; off >>= 1)
            mx = fmaxf(mx, __shfl_xor_sync(0xffffffffu, mx, off));
        float sum = 0.f;
        for (int j = lane; j < vlen; j += 32) {
            float e = __expf(sS[r * SLD + j] - mx);
            sS[r * SLD + j] = e;
            sum += e;
        }
        #pragma unroll
        for (int off = 16; off > 0; off >>= 1)
            sum += __shfl_xor_sync(0xffffffffu, sum, off);
        float inv = 1.0f / sum;
        for (int j = lane; j < vlen; j += 32) sS[r * SLD + j] *= inv;
        for (int j = vlen + lane; j < L; j += 32) sS[r * SLD + j] = 0.f;
    }

    // ---- O phase: O = P V, P converted to fp16 per tile ----
    wmma::fragment<wmma::accumulator, 16, 16, 16, float> oacc[2];
    #pragma unroll
    for (int j = 0; j < 2; j++) wmma::fill_fragment(oacc[j], 0.0f);

    for (int kt = 0; kt < nkt; kt++) {
        cp_wait_all();
        __syncthreads();
        if (kt + 1 < nkt) load_tile(vbase, kt + 1, sKV + ((kt + 1) & 1) * 64 * QLDH);
        const __half* cV = sKV + (kt & 1) * 64 * QLDH;

        // convert this 64x64 P tile to fp16
        #pragma unroll
        for (int it = 0; it < 16; it++) {
            int idx = it * 256 + tid;
            int r = idx >> 6, c = idx & 63;
            sP[r * QLDH + c] = __float2half_rn(sS[r * SLD + kt * 64 + c]);
        }
        __syncthreads();

        #pragma unroll
        for (int kk = 0; kk < 64; kk += 16) {
            wmma::fragment<wmma::matrix_a, 16, 16, 16, __half, wmma::row_major> af;
            wmma::load_matrix_sync(af, &sP[m_off * QLDH + kk], QLDH);
            #pragma unroll
            for (int j = 0; j < 2; j++) {
                wmma::fragment<wmma::matrix_b, 16, 16, 16, __half, wmma::row_major> bf;
                wmma::load_matrix_sync(bf, &cV[kk * QLDH + n_off + 16 * j], QLDH);
                wmma::mma_sync(oacc[j], af, bf, oacc[j]);
            }
        }
        __syncthreads();
    }

    // Stage O tile fp32 in sKV region, then emit fp16 into g_oh [B,T,C]
    float* stage = (float*)(smem + OFF_KV);   // 64 x 68 = 17408 B
    #pragma unroll
    for (int j = 0; j < 2; j++)
        wmma::store_matrix_sync(&stage[m_off * 68 + n_off + 16 * j],
                                oacc[j], 68, wmma::mem_row_major);
    __syncthreads();
    #pragma unroll
    for (int it = 0; it < 16; it++) {
        int idx = it * 256 + tid;
        int r = idx >> 6, c = idx & 63;
        o[((size_t)b * T_ + qt * 64 + r) * C_ + h * HD_ + c] =
            __float2half_rn(stage[r * 68 + c]);
    }
}

// ---------------------------------------------------------------------------
extern "C" void kernel_launch(void* const* d_in, const int* in_sizes, int n_in,
                              void* d_out, int out_size)
{
    const float* x    = (const float*)d_in[0];
    const float* Wqkv = (const float*)d_in[1];
    const float* Wout = (const float*)d_in[2];
    const float* cosb = (const float*)d_in[3];
    const float* sinb = (const float*)d_in[4];
    float* out = (float*)d_out;

    __half *xh, *wqkvh, *wouth, *qh, *kh, *vh, *oh;
    cudaGetSymbolAddress((void**)&xh,    g_xh);
    cudaGetSymbolAddress((void**)&wqkvh, g_wqkvh);
    cudaGetSymbolAddress((void**)&wouth, g_wouth);
    cudaGetSymbolAddress((void**)&qh,    g_qh);
    cudaGetSymbolAddress((void**)&kh,    g_kh);
    cudaGetSymbolAddress((void**)&vh,    g_vh);
    cudaGetSymbolAddress((void**)&oh,    g_oh);

    const int M = B_ * T_;

    cudaFuncSetAttribute(gemm_h<0>,
                         cudaFuncAttributeMaxDynamicSharedMemorySize, GEMM_SMEM_H);
    cudaFuncSetAttribute(gemm_h<1>,
                         cudaFuncAttributeMaxDynamicSharedMemorySize, GEMM_SMEM_H);
    cudaFuncSetAttribute(attn_kernel,
                         cudaFuncAttributeMaxDynamicSharedMemorySize, ATTN_SMEM);

    // converts
    cvt_f2h<<<(B_ * T_ * C_) / 2048, 256>>>(x, xh);
    cvt_f2h<<<(3 * C_ * C_) / 2048, 256>>>(Wqkv, wqkvh);
    cvt_f2h<<<(C_ * C_) / 2048, 256>>>(Wout, wouth);

    // K1: qkv GEMM (fp16) + fused RoPE/split/transpose
    {
        dim3 grid((3 * C_) / 64, M / 128);
        gemm_h<1><<<grid, 256, GEMM_SMEM_H>>>(
            xh, wqkvh, nullptr, cosb, sinb, qh, kh, vh, M, 3 * C_, C_);
    }
    // K2: causal attention
    {
        dim3 grid(T_ / 64, NH_, B_);
        attn_kernel<<<grid, 256, ATTN_SMEM>>>(qh, kh, vh, oh);
    }
    // K3: out = o @ Wout^T (fp32 output)
    {
        dim3 grid(C_ / 64, M / 128);
        gemm_h<0><<<grid, 256, GEMM_SMEM_H>>>(
            oh, wouth, out, nullptr, nullptr, nullptr, nullptr, nullptr,
            M, C_, C_);
    }
}

// round 6
// speedup vs baseline: 2.2414x; 1.0235x over previous
#include <cuda_runtime.h>
#include <cuda_fp16.h>
#include <cstdint>
#include <mma.h>

using namespace nvcuda;

#define B_  128
#define T_  512
#define C_  384
#define NH_ 6
#define HD_ 64

// ---------------- scratch (device globals: allocation-free) ----------------
__device__ __half g_xh[(size_t)B_ * T_ * C_];
__device__ __half g_wqkvh[(size_t)3 * C_ * C_];
__device__ __half g_wouth[(size_t)C_ * C_];
__device__ __half g_qh[(size_t)B_ * NH_ * T_ * HD_];
__device__ __half g_kh[(size_t)B_ * NH_ * T_ * HD_];
__device__ __half g_vh[(size_t)B_ * NH_ * T_ * HD_];
__device__ __half g_oh[(size_t)B_ * T_ * C_];

// ---------------- cp.async helpers ----------------
__device__ __forceinline__ void cp_async16(void* smem, const void* gmem) {
    unsigned s = (unsigned)__cvta_generic_to_shared(smem);
    asm volatile("cp.async.cg.shared.global [%0], [%1], 16;\n" :: "r"(s), "l"(gmem));
}
__device__ __forceinline__ void cp_commit() {
    asm volatile("cp.async.commit_group;\n");
}
__device__ __forceinline__ void cp_wait_all() {
    asm volatile("cp.async.wait_group 0;\n");
}

// ---------------------------------------------------------------------------
// fp32 -> fp16 converter (vectorized, n multiple of 2048)
// ---------------------------------------------------------------------------
__global__ void cvt_f2h(const float* __restrict__ in, __half* __restrict__ out) {
    size_t i = ((size_t)blockIdx.x * blockDim.x + threadIdx.x) * 8;
    float4 a = *(const float4*)(in + i);
    float4 b = *(const float4*)(in + i + 4);
    __half2 h0 = __floats2half2_rn(a.x, a.y);
    __half2 h1 = __floats2half2_rn(a.z, a.w);
    __half2 h2 = __floats2half2_rn(b.x, b.y);
    __half2 h3 = __floats2half2_rn(b.z, b.w);
    uint4 pack;
    pack.x = *(unsigned*)&h0; pack.y = *(unsigned*)&h1;
    pack.z = *(unsigned*)&h2; pack.w = *(unsigned*)&h3;
    *(uint4*)(out + i) = pack;
}

// ===========================================================================
// fp16 GEMM (NT): C[M,N] = A[M,K] @ B[N,K]^T, fp32 accumulate. (as round 5)
// ===========================================================================
#define LDH 40
#define GEMM_SMEM_H 34816

template <int EPI>
__global__ void __launch_bounds__(256) gemm_h(
    const __half* __restrict__ A, const __half* __restrict__ Bw,
    float* __restrict__ Cc,
    const float* __restrict__ cosb, const float* __restrict__ sinb,
    __half* __restrict__ qo, __half* __restrict__ ko, __half* __restrict__ vo,
    int M, int N, int K)
{
    extern __shared__ char smem[];
    __half* sAh = (__half*)smem;
    __half* sBh = (__half*)smem + 2 * 128 * LDH;

    const int tid = threadIdx.x;
    const int w   = tid >> 5;
    const int bm  = blockIdx.y * 128;
    const int bn  = blockIdx.x * 64;
    const int m_off = (w >> 1) * 32;
    const int n_off = (w & 1) * 32;

    wmma::fragment<wmma::accumulator, 16, 16, 16, float> acc[2][2];
    #pragma unroll
    for (int i = 0; i < 2; i++)
        #pragma unroll
        for (int j = 0; j < 2; j++)
            wmma::fill_fragment(acc[i][j], 0.0f);

    auto load_stage = [&](int k0, int st) {
        __half* dA = sAh + st * 128 * LDH;
        __half* dB = sBh + st * 64 * LDH;
        #pragma unroll
        for (int p = 0; p < 2; p++) {
            int c = p * 256 + tid;
            int r = c >> 2, c8 = (c & 3) * 8;
            cp_async16(&dA[r * LDH + c8], &A[(size_t)(bm + r) * K + k0 + c8]);
        }
        {
            int r = tid >> 2, c8 = (tid & 3) * 8;
            cp_async16(&dB[r * LDH + c8], &Bw[(size_t)(bn + r) * K + k0 + c8]);
        }
        cp_commit();
    };

    load_stage(0, 0);
    const int nk = K / 32;

    for (int ki = 0; ki < nk; ki++) {
        cp_wait_all();
        __syncthreads();
        if (ki + 1 < nk) load_stage((ki + 1) * 32, (ki + 1) & 1);

        const __half* cA = sAh + (ki & 1) * 128 * LDH;
        const __half* cB = sBh + (ki & 1) * 64 * LDH;

        #pragma unroll
        for (int kk = 0; kk < 32; kk += 16) {
            wmma::fragment<wmma::matrix_a, 16, 16, 16, __half, wmma::row_major> af[2];
            wmma::fragment<wmma::matrix_b, 16, 16, 16, __half, wmma::col_major> bf[2];
            #pragma unroll
            for (int i = 0; i < 2; i++)
                wmma::load_matrix_sync(af[i], &cA[(m_off + 16 * i) * LDH + kk], LDH);
            #pragma unroll
            for (int j = 0; j < 2; j++)
                wmma::load_matrix_sync(bf[j], &cB[(n_off + 16 * j) * LDH + kk], LDH);
            #pragma unroll
            for (int i = 0; i < 2; i++)
                #pragma unroll
                for (int j = 0; j < 2; j++)
                    wmma::mma_sync(acc[i][j], af[i], bf[j], acc[i][j]);
        }
        __syncthreads();
    }

    if (EPI == 0) {
        #pragma unroll
        for (int i = 0; i < 2; i++)
            #pragma unroll
            for (int j = 0; j < 2; j++)
                wmma::store_matrix_sync(
                    &Cc[(size_t)(bm + m_off + 16 * i) * N + bn + n_off + 16 * j],
                    acc[i][j], N, wmma::mem_row_major);
    } else {
        float* sC = (float*)smem;   // 128 x 68
        #pragma unroll
        for (int i = 0; i < 2; i++)
            #pragma unroll
            for (int j = 0; j < 2; j++)
                wmma::store_matrix_sync(&sC[(m_off + 16 * i) * 68 + n_off + 16 * j],
                                        acc[i][j], 68, wmma::mem_row_major);
        __syncthreads();

        const int g  = bn >> 6;
        const int i3 = g / NH_;
        const int hh = g % NH_;

        #pragma unroll
        for (int it = 0; it < 32; it++) {
            int idx = it * 256 + tid;
            int r = idx >> 6, d = idx & 63;
            int gm = bm + r;
            int b = gm >> 9, t = gm & 511;
            float val = sC[r * 68 + d];
            if (i3 < 2 && d < 16) {
                if (d < 8) {
                    float c = cosb[t * 8 + d], s = sinb[t * 8 + d];
                    val = val * c - sC[r * 68 + d + 8] * s;
                } else {
                    int jj = d - 8;
                    float c = cosb[t * 8 + jj], s = sinb[t * 8 + jj];
                    val = val * c + sC[r * 68 + d - 8] * s;
                }
            }
            size_t off = (((size_t)b * NH_ + hh) * T_ + t) * HD_ + d;
            if (i3 == 0)      qo[off] = __float2half_rn(val * 0.125f);
            else if (i3 == 1) ko[off] = __float2half_rn(val);
            else              vo[off] = __float2half_rn(val);
        }
    }
}

// ===========================================================================
// Attention v2: q-tile 128 rows, fp16 score strip, fp16-acc for S,
// fp32-acc for O. One block per (b, h, qt2 of 4). 256 threads / 8 warps.
// smem: sQ h[128][72] | sKV h[2][64][72] | sS h[128][520]
// ===========================================================================
#define QLDH 72
#define SLDH 520
#define OFF_KV  (128 * QLDH * 2)                 // 18432
#define OFF_S   (OFF_KV + 2 * 64 * QLDH * 2)     // 36864
#define ATTN_SMEM (OFF_S + 128 * SLDH * 2)       // 169984 B

__global__ void __launch_bounds__(256) attn_kernel(
    const __half* __restrict__ q, const __half* __restrict__ k,
    const __half* __restrict__ v, __half* __restrict__ o)
{
    extern __shared__ char smem[];
    __half* sQ  = (__half*)smem;
    __half* sKV = (__half*)(smem + OFF_KV);
    __half* sS  = (__half*)(smem + OFF_S);

    const int qt = blockIdx.x;     // 0..3 (128-row q tiles)
    const int h  = blockIdx.y, b = blockIdx.z;
    const int tid = threadIdx.x, w = tid >> 5, lane = tid & 31;
    const int nkt = 2 * (qt + 1);  // 64-row k tiles

    const __half* qbase = q + (((size_t)b * NH_ + h) * T_ + qt * 128) * HD_;
    const __half* kbase = k + (((size_t)b * NH_ + h) * T_) * HD_;
    const __half* vbase = v + (((size_t)b * NH_ + h) * T_) * HD_;

    auto load_tile = [&](const __half* base, int kt, __half* dst) {
        int lr = tid >> 2, c8 = (tid & 3) * 8;
        #pragma unroll
        for (int p = 0; p < 2; p++) {
            int c = c8 + p * 32;
            cp_async16(&dst[lr * QLDH + c], &base[(kt * 64 + lr) * 64 + c]);
        }
        cp_commit();
    };

    // Q tile (128x64) + K0 prefetch
    {
        #pragma unroll
        for (int p = 0; p < 4; p++) {
            int idx = p * 256 + tid;
            int r = idx >> 3, c8 = (idx & 7) * 8;
            cp_async16(&sQ[r * QLDH + c8], &qbase[r * 64 + c8]);
        }
        load_tile(kbase, 0, sKV);
    }

    // ---- S phase: warp tile 32x32 over 128x64 ----
    const int ms = (w >> 1) * 32;
    const int ns = (w & 1) * 32;

    for (int kt = 0; kt < nkt; kt++) {
        cp_wait_all();
        __syncthreads();
        if (kt + 1 < nkt) load_tile(kbase, kt + 1, sKV + ((kt + 1) & 1) * 64 * QLDH);
        const __half* cK = sKV + (kt & 1) * 64 * QLDH;

        wmma::fragment<wmma::accumulator, 16, 16, 16, __half> sc[2][2];
        #pragma unroll
        for (int i = 0; i < 2; i++)
            #pragma unroll
            for (int j = 0; j < 2; j++)
                wmma::fill_fragment(sc[i][j], __float2half(0.0f));

        #pragma unroll
        for (int kk = 0; kk < 64; kk += 16) {
            wmma::fragment<wmma::matrix_a, 16, 16, 16, __half, wmma::row_major> af[2];
            wmma::fragment<wmma::matrix_b, 16, 16, 16, __half, wmma::col_major> bf[2];
            #pragma unroll
            for (int i = 0; i < 2; i++)
                wmma::load_matrix_sync(af[i], &sQ[(ms + 16 * i) * QLDH + kk], QLDH);
            #pragma unroll
            for (int j = 0; j < 2; j++)
                wmma::load_matrix_sync(bf[j], &cK[(ns + 16 * j) * QLDH + kk], QLDH);
            #pragma unroll
            for (int i = 0; i < 2; i++)
                #pragma unroll
                for (int j = 0; j < 2; j++)
                    wmma::mma_sync(sc[i][j], af[i], bf[j], sc[i][j]);
        }
        #pragma unroll
        for (int i = 0; i < 2; i++)
            #pragma unroll
            for (int j = 0; j < 2; j++)
                wmma::store_matrix_sync(
                    &sS[(ms + 16 * i) * SLDH + kt * 64 + ns + 16 * j],
                    sc[i][j], SLDH, wmma::mem_row_major);
        __syncthreads();
    }

    // Prefetch V0 during softmax
    load_tile(vbase, 0, sKV);

    // ---- softmax (causal, fp32 math on fp16 strip): warp w -> 16 rows ----
    const int L = nkt * 64;
    for (int rr = 0; rr < 16; rr++) {
        int r    = w * 16 + rr;
        int vlen = qt * 128 + r + 1;
        float mx = -1e30f;
        for (int j = lane; j < vlen; j += 32)
            mx = fmaxf(mx, __half2float(sS[r * SLDH + j]));
        #pragma unroll
        for (int off = 16; off > 0; off >>= 1)
            mx = fmaxf(mx, __shfl_xor_sync(0xffffffffu, mx, off));
        float sum = 0.f;
        for (int j = lane; j < vlen; j += 32) {
            float e = __expf(__half2float(sS[r * SLDH + j]) - mx);
            sS[r * SLDH + j] = __float2half_rn(e);
            sum += e;
        }
        #pragma unroll
        for (int off = 16; off > 0; off >>= 1)
            sum += __shfl_xor_sync(0xffffffffu, sum, off);
        float inv = 1.0f / sum;
        for (int j = lane; j < vlen; j += 32)
            sS[r * SLDH + j] = __float2half_rn(__half2float(sS[r * SLDH + j]) * inv);
        for (int j = vlen + lane; j < L; j += 32)
            sS[r * SLDH + j] = __float2half_rn(0.0f);
    }

    // ---- O phase: warp tile 16x64, fp32 acc ----
    const int mo = w * 16;
    wmma::fragment<wmma::accumulator, 16, 16, 16, float> oacc[4];
    #pragma unroll
    for (int j = 0; j < 4; j++) wmma::fill_fragment(oacc[j], 0.0f);

    for (int kt = 0; kt < nkt; kt++) {
        cp_wait_all();
        __syncthreads();
        if (kt + 1 < nkt) load_tile(vbase, kt + 1, sKV + ((kt + 1) & 1) * 64 * QLDH);
        const __half* cV = sKV + (kt & 1) * 64 * QLDH;

        #pragma unroll
        for (int kk = 0; kk < 64; kk += 16) {
            wmma::fragment<wmma::matrix_a, 16, 16, 16, __half, wmma::row_major> af;
            wmma::load_matrix_sync(af, &sS[mo * SLDH + kt * 64 + kk], SLDH);
            #pragma unroll
            for (int j = 0; j < 4; j++) {
                wmma::fragment<wmma::matrix_b, 16, 16, 16, __half, wmma::row_major> bf;
                wmma::load_matrix_sync(bf, &cV[kk * QLDH + 16 * j], QLDH);
                wmma::mma_sync(oacc[j], af, bf, oacc[j]);
            }
        }
        __syncthreads();
    }

    // ---- emit O (fp32 stage in sQ/sKV region -> fp16 g_oh) ----
    float* stage = (float*)smem;   // 128 x 68 floats = 34816 B (fits in 36864)
    #pragma unroll
    for (int j = 0; j < 4; j++)
        wmma::store_matrix_sync(&stage[mo * 68 + 16 * j], oacc[j], 68,
                                wmma::mem_row_major);
    __syncthreads();
    #pragma unroll
    for (int it = 0; it < 32; it++) {
        int idx = it * 256 + tid;
        int r = idx >> 6, c = idx & 63;
        o[((size_t)b * T_ + qt * 128 + r) * C_ + h * HD_ + c] =
            __float2half_rn(stage[r * 68 + c]);
    }
}

// ---------------------------------------------------------------------------
extern "C" void kernel_launch(void* const* d_in, const int* in_sizes, int n_in,
                              void* d_out, int out_size)
{
    const float* x    = (const float*)d_in[0];
    const float* Wqkv = (const float*)d_in[1];
    const float* Wout = (const float*)d_in[2];
    const float* cosb = (const float*)d_in[3];
    const float* sinb = (const float*)d_in[4];
    float* out = (float*)d_out;

    __half *xh, *wqkvh, *wouth, *qh, *kh, *vh, *oh;
    cudaGetSymbolAddress((void**)&xh,    g_xh);
    cudaGetSymbolAddress((void**)&wqkvh, g_wqkvh);
    cudaGetSymbolAddress((void**)&wouth, g_wouth);
    cudaGetSymbolAddress((void**)&qh,    g_qh);
    cudaGetSymbolAddress((void**)&kh,    g_kh);
    cudaGetSymbolAddress((void**)&vh,    g_vh);
    cudaGetSymbolAddress((void**)&oh,    g_oh);

    const int M = B_ * T_;

    cudaFuncSetAttribute(gemm_h<0>,
                         cudaFuncAttributeMaxDynamicSharedMemorySize, GEMM_SMEM_H);
    cudaFuncSetAttribute(gemm_h<1>,
                         cudaFuncAttributeMaxDynamicSharedMemorySize, GEMM_SMEM_H);
    cudaFuncSetAttribute(attn_kernel,
                         cudaFuncAttributeMaxDynamicSharedMemorySize, ATTN_SMEM);

    cvt_f2h<<<(B_ * T_ * C_) / 2048, 256>>>(x, xh);
    cvt_f2h<<<(3 * C_ * C_) / 2048, 256>>>(Wqkv, wqkvh);
    cvt_f2h<<<(C_ * C_) / 2048, 256>>>(Wout, wouth);

    // K1: qkv GEMM (fp16) + fused RoPE/split/transpose
    {
        dim3 grid((3 * C_) / 64, M / 128);
        gemm_h<1><<<grid, 256, GEMM_SMEM_H>>>(
            xh, wqkvh, nullptr, cosb, sinb, qh, kh, vh, M, 3 * C_, C_);
    }
    // K2: causal attention (q-tile 128, fp16 strip)
    {
        dim3 grid(T_ / 128, NH_, B_);
        attn_kernel<<<grid, 256, ATTN_SMEM>>>(qh, kh, vh, oh);
    }
    // K3: out = o @ Wout^T (fp32 output)
    {
        dim3 grid(C_ / 64, M / 128);
        gemm_h<0><<<grid, 256, GEMM_SMEM_H>>>(
            oh, wouth, out, nullptr, nullptr, nullptr, nullptr, nullptr,
            M, C_, C_);
    }
}

// round 7
// speedup vs baseline: 3.2482x; 1.4492x over previous
#include <cuda_runtime.h>
#include <cuda_fp16.h>
#include <cstdint>
#include <mma.h>

using namespace nvcuda;

#define B_  128
#define T_  512
#define C_  384
#define NH_ 6
#define HD_ 64

// ---------------- scratch (device globals: allocation-free) ----------------
__device__ __half g_xh[(size_t)B_ * T_ * C_];
__device__ __half g_wqkvh[(size_t)3 * C_ * C_];
__device__ __half g_wouth[(size_t)C_ * C_];
__device__ __half g_qh[(size_t)B_ * NH_ * T_ * HD_];
__device__ __half g_kh[(size_t)B_ * NH_ * T_ * HD_];
__device__ __half g_vh[(size_t)B_ * NH_ * T_ * HD_];
__device__ __half g_oh[(size_t)B_ * T_ * C_];

// ---------------- cp.async helpers ----------------
__device__ __forceinline__ void cp_async16(void* smem, const void* gmem) {
    unsigned s = (unsigned)__cvta_generic_to_shared(smem);
    asm volatile("cp.async.cg.shared.global [%0], [%1], 16;\n" :: "r"(s), "l"(gmem));
}
__device__ __forceinline__ void cp_commit() {
    asm volatile("cp.async.commit_group;\n");
}
__device__ __forceinline__ void cp_wait_all() {
    asm volatile("cp.async.wait_group 0;\n");
}

// ---------------------------------------------------------------------------
// fp32 -> fp16 converter (vectorized, n multiple of 2048)
// ---------------------------------------------------------------------------
__global__ void cvt_f2h(const float* __restrict__ in, __half* __restrict__ out) {
    size_t i = ((size_t)blockIdx.x * blockDim.x + threadIdx.x) * 8;
    float4 a = *(const float4*)(in + i);
    float4 b = *(const float4*)(in + i + 4);
    __half2 h0 = __floats2half2_rn(a.x, a.y);
    __half2 h1 = __floats2half2_rn(a.z, a.w);
    __half2 h2 = __floats2half2_rn(b.x, b.y);
    __half2 h3 = __floats2half2_rn(b.z, b.w);
    uint4 pack;
    pack.x = *(unsigned*)&h0; pack.y = *(unsigned*)&h1;
    pack.z = *(unsigned*)&h2; pack.w = *(unsigned*)&h3;
    *(uint4*)(out + i) = pack;
}

// ===========================================================================
// fp16 GEMM (NT): C[M,N] = A[M,K] @ B[N,K]^T, fp32 accumulate. (as round 5)
// ===========================================================================
#define LDH 40
#define GEMM_SMEM_H 34816

template <int EPI>
__global__ void __launch_bounds__(256) gemm_h(
    const __half* __restrict__ A, const __half* __restrict__ Bw,
    float* __restrict__ Cc,
    const float* __restrict__ cosb, const float* __restrict__ sinb,
    __half* __restrict__ qo, __half* __restrict__ ko, __half* __restrict__ vo,
    int M, int N, int K)
{
    extern __shared__ char smem[];
    __half* sAh = (__half*)smem;
    __half* sBh = (__half*)smem + 2 * 128 * LDH;

    const int tid = threadIdx.x;
    const int w   = tid >> 5;
    const int bm  = blockIdx.y * 128;
    const int bn  = blockIdx.x * 64;
    const int m_off = (w >> 1) * 32;
    const int n_off = (w & 1) * 32;

    wmma::fragment<wmma::accumulator, 16, 16, 16, float> acc[2][2];
    #pragma unroll
    for (int i = 0; i < 2; i++)
        #pragma unroll
        for (int j = 0; j < 2; j++)
            wmma::fill_fragment(acc[i][j], 0.0f);

    auto load_stage = [&](int k0, int st) {
        __half* dA = sAh + st * 128 * LDH;
        __half* dB = sBh + st * 64 * LDH;
        #pragma unroll
        for (int p = 0; p < 2; p++) {
            int c = p * 256 + tid;
            int r = c >> 2, c8 = (c & 3) * 8;
            cp_async16(&dA[r * LDH + c8], &A[(size_t)(bm + r) * K + k0 + c8]);
        }
        {
            int r = tid >> 2, c8 = (tid & 3) * 8;
            cp_async16(&dB[r * LDH + c8], &Bw[(size_t)(bn + r) * K + k0 + c8]);
        }
        cp_commit();
    };

    load_stage(0, 0);
    const int nk = K / 32;

    for (int ki = 0; ki < nk; ki++) {
        cp_wait_all();
        __syncthreads();
        if (ki + 1 < nk) load_stage((ki + 1) * 32, (ki + 1) & 1);

        const __half* cA = sAh + (ki & 1) * 128 * LDH;
        const __half* cB = sBh + (ki & 1) * 64 * LDH;

        #pragma unroll
        for (int kk = 0; kk < 32; kk += 16) {
            wmma::fragment<wmma::matrix_a, 16, 16, 16, __half, wmma::row_major> af[2];
            wmma::fragment<wmma::matrix_b, 16, 16, 16, __half, wmma::col_major> bf[2];
            #pragma unroll
            for (int i = 0; i < 2; i++)
                wmma::load_matrix_sync(af[i], &cA[(m_off + 16 * i) * LDH + kk], LDH);
            #pragma unroll
            for (int j = 0; j < 2; j++)
                wmma::load_matrix_sync(bf[j], &cB[(n_off + 16 * j) * LDH + kk], LDH);
            #pragma unroll
            for (int i = 0; i < 2; i++)
                #pragma unroll
                for (int j = 0; j < 2; j++)
                    wmma::mma_sync(acc[i][j], af[i], bf[j], acc[i][j]);
        }
        __syncthreads();
    }

    if (EPI == 0) {
        #pragma unroll
        for (int i = 0; i < 2; i++)
            #pragma unroll
            for (int j = 0; j < 2; j++)
                wmma::store_matrix_sync(
                    &Cc[(size_t)(bm + m_off + 16 * i) * N + bn + n_off + 16 * j],
                    acc[i][j], N, wmma::mem_row_major);
    } else {
        float* sC = (float*)smem;   // 128 x 68
        #pragma unroll
        for (int i = 0; i < 2; i++)
            #pragma unroll
            for (int j = 0; j < 2; j++)
                wmma::store_matrix_sync(&sC[(m_off + 16 * i) * 68 + n_off + 16 * j],
                                        acc[i][j], 68, wmma::mem_row_major);
        __syncthreads();

        const int g  = bn >> 6;
        const int i3 = g / NH_;
        const int hh = g % NH_;

        #pragma unroll
        for (int it = 0; it < 32; it++) {
            int idx = it * 256 + tid;
            int r = idx >> 6, d = idx & 63;
            int gm = bm + r;
            int b = gm >> 9, t = gm & 511;
            float val = sC[r * 68 + d];
            if (i3 < 2 && d < 16) {
                if (d < 8) {
                    float c = cosb[t * 8 + d], s = sinb[t * 8 + d];
                    val = val * c - sC[r * 68 + d + 8] * s;
                } else {
                    int jj = d - 8;
                    float c = cosb[t * 8 + jj], s = sinb[t * 8 + jj];
                    val = val * c + sC[r * 68 + d - 8] * s;
                }
            }
            size_t off = (((size_t)b * NH_ + hh) * T_ + t) * HD_ + d;
            if (i3 == 0)      qo[off] = __float2half_rn(val * 0.125f);
            else if (i3 == 1) ko[off] = __float2half_rn(val);
            else              vo[off] = __float2half_rn(val);
        }
    }
}

// ===========================================================================
// Attention v3: q-tile 64, fp16 strip, fp16 S-acc, fp32 O-acc.
// 2 CTAs/SM (94 KB smem). One block per (b, h, qt of 8). 256 thr / 8 warps.
// smem: sQ h[64][72] | sKV h[2][64][72] | sS h[64][520]
// ===========================================================================
#define QLDH 72
#define SLDH 520
#define OFF_KV  (64 * QLDH * 2)                  // 9216
#define OFF_S   (OFF_KV + 2 * 64 * QLDH * 2)     // 27648
#define ATTN_SMEM (OFF_S + 64 * SLDH * 2)        // 94208 B

__global__ void __launch_bounds__(256, 2) attn_kernel(
    const __half* __restrict__ q, const __half* __restrict__ k,
    const __half* __restrict__ v, __half* __restrict__ o)
{
    extern __shared__ char smem[];
    __half* sQ  = (__half*)smem;
    __half* sKV = (__half*)(smem + OFF_KV);
    __half* sS  = (__half*)(smem + OFF_S);

    const int qt = blockIdx.x;     // 0..7
    const int h  = blockIdx.y, b = blockIdx.z;
    const int tid = threadIdx.x, w = tid >> 5, lane = tid & 31;
    const int nkt = qt + 1;

    const __half* qbase = q + (((size_t)b * NH_ + h) * T_ + qt * 64) * HD_;
    const __half* kbase = k + (((size_t)b * NH_ + h) * T_) * HD_;
    const __half* vbase = v + (((size_t)b * NH_ + h) * T_) * HD_;

    auto load_tile = [&](const __half* base, int kt, __half* dst) {
        int lr = tid >> 2, c8 = (tid & 3) * 8;
        #pragma unroll
        for (int p = 0; p < 2; p++) {
            int c = c8 + p * 32;
            cp_async16(&dst[lr * QLDH + c], &base[(kt * 64 + lr) * 64 + c]);
        }
        cp_commit();
    };

    // Q tile (64x64) + K0 prefetch
    {
        int lr = tid >> 2, c8 = (tid & 3) * 8;
        #pragma unroll
        for (int p = 0; p < 2; p++) {
            int c = c8 + p * 32;
            cp_async16(&sQ[lr * QLDH + c], &qbase[lr * 64 + c]);
        }
        load_tile(kbase, 0, sKV);
    }

    // warp layout: 4 row-groups x 2 col-groups (tile 16x32)
    const int ms = (w >> 1) * 16;
    const int ns = (w & 1) * 32;

    // ---- S phase ----
    for (int kt = 0; kt < nkt; kt++) {
        cp_wait_all();
        __syncthreads();
        if (kt + 1 < nkt) load_tile(kbase, kt + 1, sKV + ((kt + 1) & 1) * 64 * QLDH);
        const __half* cK = sKV + (kt & 1) * 64 * QLDH;

        wmma::fragment<wmma::accumulator, 16, 16, 16, __half> sc[2];
        #pragma unroll
        for (int j = 0; j < 2; j++) wmma::fill_fragment(sc[j], __float2half(0.0f));

        #pragma unroll
        for (int kk = 0; kk < 64; kk += 16) {
            wmma::fragment<wmma::matrix_a, 16, 16, 16, __half, wmma::row_major> af;
            wmma::load_matrix_sync(af, &sQ[ms * QLDH + kk], QLDH);
            #pragma unroll
            for (int j = 0; j < 2; j++) {
                wmma::fragment<wmma::matrix_b, 16, 16, 16, __half, wmma::col_major> bf;
                wmma::load_matrix_sync(bf, &cK[(ns + 16 * j) * QLDH + kk], QLDH);
                wmma::mma_sync(sc[j], af, bf, sc[j]);
            }
        }
        #pragma unroll
        for (int j = 0; j < 2; j++)
            wmma::store_matrix_sync(&sS[ms * SLDH + kt * 64 + ns + 16 * j],
                                    sc[j], SLDH, wmma::mem_row_major);
        __syncthreads();
    }

    // Prefetch V0 during softmax
    load_tile(vbase, 0, sKV);

    // ---- softmax (causal, fp32 math, half2-vectorized): warp w -> 8 rows ----
    const int L = nkt * 64;
    for (int rr = 0; rr < 8; rr++) {
        int r    = w * 8 + rr;
        int vlen = qt * 64 + r + 1;
        int n2   = vlen >> 1;
        __half2* row2 = (__half2*)&sS[r * SLDH];

        float mx = -1e30f;
        for (int j = lane; j < n2; j += 32) {
            float2 f = __half22float2(row2[j]);
            mx = fmaxf(mx, fmaxf(f.x, f.y));
        }
        if ((vlen & 1) && lane == 0)
            mx = fmaxf(mx, __half2float(sS[r * SLDH + vlen - 1]));
        #pragma unroll
        for (int off = 16; off > 0; off >>= 1)
            mx = fmaxf(mx, __shfl_xor_sync(0xffffffffu, mx, off));

        float sum = 0.f;
        for (int j = lane; j < n2; j += 32) {
            float2 f = __half22float2(row2[j]);
            float e0 = __expf(f.x - mx), e1 = __expf(f.y - mx);
            row2[j] = __floats2half2_rn(e0, e1);
            sum += e0 + e1;
        }
        if ((vlen & 1) && lane == 0) {
            float e = __expf(__half2float(sS[r * SLDH + vlen - 1]) - mx);
            sS[r * SLDH + vlen - 1] = __float2half_rn(e);
            sum += e;
        }
        #pragma unroll
        for (int off = 16; off > 0; off >>= 1)
            sum += __shfl_xor_sync(0xffffffffu, sum, off);

        float inv = 1.0f / sum;
        __half2 inv2 = __floats2half2_rn(inv, inv);
        for (int j = lane; j < n2; j += 32)
            row2[j] = __hmul2(row2[j], inv2);
        if ((vlen & 1) && lane == 0)
            sS[r * SLDH + vlen - 1] =
                __float2half_rn(__half2float(sS[r * SLDH + vlen - 1]) * inv);
        for (int j = vlen + lane; j < L; j += 32)
            sS[r * SLDH + j] = __float2half_rn(0.0f);
    }

    // ---- O phase: warp tile 16x32, fp32 acc ----
    wmma::fragment<wmma::accumulator, 16, 16, 16, float> oacc[2];
    #pragma unroll
    for (int j = 0; j < 2; j++) wmma::fill_fragment(oacc[j], 0.0f);

    for (int kt = 0; kt < nkt; kt++) {
        cp_wait_all();
        __syncthreads();
        if (kt + 1 < nkt) load_tile(vbase, kt + 1, sKV + ((kt + 1) & 1) * 64 * QLDH);
        const __half* cV = sKV + (kt & 1) * 64 * QLDH;

        #pragma unroll
        for (int kk = 0; kk < 64; kk += 16) {
            wmma::fragment<wmma::matrix_a, 16, 16, 16, __half, wmma::row_major> af;
            wmma::load_matrix_sync(af, &sS[ms * SLDH + kt * 64 + kk], SLDH);
            #pragma unroll
            for (int j = 0; j < 2; j++) {
                wmma::fragment<wmma::matrix_b, 16, 16, 16, __half, wmma::row_major> bf;
                wmma::load_matrix_sync(bf, &cV[kk * QLDH + ns + 16 * j], QLDH);
                wmma::mma_sync(oacc[j], af, bf, oacc[j]);
            }
        }
        __syncthreads();
    }

    // ---- emit O (fp32 stage in strip region -> fp16 g_oh) ----
    float* stage = (float*)(smem + OFF_S);   // 64 x 68 floats = 17408 B
    #pragma unroll
    for (int j = 0; j < 2; j++)
        wmma::store_matrix_sync(&stage[ms * 68 + ns + 16 * j], oacc[j], 68,
                                wmma::mem_row_major);
    __syncthreads();
    #pragma unroll
    for (int it = 0; it < 16; it++) {
        int idx = it * 256 + tid;
        int r = idx >> 6, c = idx & 63;
        o[((size_t)b * T_ + qt * 64 + r) * C_ + h * HD_ + c] =
            __float2half_rn(stage[r * 68 + c]);
    }
}

// ---------------------------------------------------------------------------
extern "C" void kernel_launch(void* const* d_in, const int* in_sizes, int n_in,
                              void* d_out, int out_size)
{
    const float* x    = (const float*)d_in[0];
    const float* Wqkv = (const float*)d_in[1];
    const float* Wout = (const float*)d_in[2];
    const float* cosb = (const float*)d_in[3];
    const float* sinb = (const float*)d_in[4];
    float* out = (float*)d_out;

    __half *xh, *wqkvh, *wouth, *qh, *kh, *vh, *oh;
    cudaGetSymbolAddress((void**)&xh,    g_xh);
    cudaGetSymbolAddress((void**)&wqkvh, g_wqkvh);
    cudaGetSymbolAddress((void**)&wouth, g_wouth);
    cudaGetSymbolAddress((void**)&qh,    g_qh);
    cudaGetSymbolAddress((void**)&kh,    g_kh);
    cudaGetSymbolAddress((void**)&vh,    g_vh);
    cudaGetSymbolAddress((void**)&oh,    g_oh);

    const int M = B_ * T_;

    cudaFuncSetAttribute(gemm_h<0>,
                         cudaFuncAttributeMaxDynamicSharedMemorySize, GEMM_SMEM_H);
    cudaFuncSetAttribute(gemm_h<1>,
                         cudaFuncAttributeMaxDynamicSharedMemorySize, GEMM_SMEM_H);
    cudaFuncSetAttribute(attn_kernel,
                         cudaFuncAttributeMaxDynamicSharedMemorySize, ATTN_SMEM);

    cvt_f2h<<<(B_ * T_ * C_) / 2048, 256>>>(x, xh);
    cvt_f2h<<<(3 * C_ * C_) / 2048, 256>>>(Wqkv, wqkvh);
    cvt_f2h<<<(C_ * C_) / 2048, 256>>>(Wout, wouth);

    // K1: qkv GEMM (fp16) + fused RoPE/split/transpose
    {
        dim3 grid((3 * C_) / 64, M / 128);
        gemm_h<1><<<grid, 256, GEMM_SMEM_H>>>(
            xh, wqkvh, nullptr, cosb, sinb, qh, kh, vh, M, 3 * C_, C_);
    }
    // K2: causal attention (q-tile 64, fp16 strip, 2 CTAs/SM)
    {
        dim3 grid(T_ / 64, NH_, B_);
        attn_kernel<<<grid, 256, ATTN_SMEM>>>(qh, kh, vh, oh);
    }
    // K3: out = o @ Wout^T (fp32 output)
    {
        dim3 grid(C_ / 64, M / 128);
        gemm_h<0><<<grid, 256, GEMM_SMEM_H>>>(
            oh, wouth, out, nullptr, nullptr, nullptr, nullptr, nullptr,
            M, C_, C_);
    }
}